// round 15
// baseline (speedup 1.0000x reference)
#include <cuda_runtime.h>
#include <cuda_fp16.h>
#include <math.h>
#include <stdint.h>

#define BATCH 512
#define P 1152
#define NCAPS 10
#define T 16
#define D 8
#define PD 9216          // P*D
#define NT 160           // NCAPS*T
#define KCH1 36          // split-K chunks gemm1 (36*256 = 9216)
#define KCH2 2           // split-K chunks gemm2 (2*256 = 512)

// SMEM stage: K=32 halves (64B/row), 80B row stride.
#define SROW 80
#define B_OFF   5120             // 64*80
#define STAGE_BYTES 17920        // + 160*80
#define NSTAGE 4
#define SMEM_BYTES (NSTAGE*STAGE_BYTES)   // 71680 -> 2 CTAs/SM

// ---------------- scratch ----------------------------------------------------
__device__ __half g_Wt2h[PD*NT];      // fl16(W) [pd][nt] (gemm2 epilogue)
__device__ __half g_Xq[BATCH*PD];     // fl16(X) [b][pd]
__device__ __half g_Xtq[PD*BATCH];    // fl16(X)^T [pd][b]
__device__ __half g_Bq[NT*PD];        // fl16(c.W) [nt][pd]
__device__ __half g_vq[NT*BATCH];     // fl16(v) [nt][b]
__device__ float  g_s[BATCH*NT];      // atomically-accumulated s [b][nt]
__device__ float  g_bbar[P*NCAPS];
__device__ float  g_b[P*NCAPS];
__device__ int    g_cnt1[BATCH/64];   // split-K arrival counters (self-reset)
__device__ int    g_cnt2[PD/64];

// ---------------- PTX helpers ------------------------------------------------
__device__ __forceinline__ void mma16816(float* c,
    uint32_t a0, uint32_t a1, uint32_t a2, uint32_t a3,
    uint32_t b0, uint32_t b1) {
    asm volatile(
        "mma.sync.aligned.m16n8k16.row.col.f32.f16.f16.f32 "
        "{%0,%1,%2,%3}, {%4,%5,%6,%7}, {%8,%9}, {%0,%1,%2,%3};"
        : "+f"(c[0]), "+f"(c[1]), "+f"(c[2]), "+f"(c[3])
        : "r"(a0), "r"(a1), "r"(a2), "r"(a3), "r"(b0), "r"(b1));
}
__device__ __forceinline__ void ldmx4(uint32_t* r, uint32_t addr) {
    asm volatile("ldmatrix.sync.aligned.m8n8.x4.shared.b16 {%0,%1,%2,%3}, [%4];"
        : "=r"(r[0]), "=r"(r[1]), "=r"(r[2]), "=r"(r[3]) : "r"(addr));
}
__device__ __forceinline__ void ldmx2(uint32_t* r, uint32_t addr) {
    asm volatile("ldmatrix.sync.aligned.m8n8.x2.shared.b16 {%0,%1}, [%2];"
        : "=r"(r[0]), "=r"(r[1]) : "r"(addr));
}
__device__ __forceinline__ uint32_t s2u(const void* p) {
    uint32_t a;
    asm("{ .reg .u64 t; cvta.to.shared.u64 t, %1; cvt.u32.u64 %0, t; }"
        : "=r"(a) : "l"(p));
    return a;
}
__device__ __forceinline__ void cpasync16(uint32_t dst, const void* src) {
    asm volatile("cp.async.cg.shared.global [%0], [%1], 16;"
        :: "r"(dst), "l"(__cvta_generic_to_global(src)));
}
#define CP_COMMIT() asm volatile("cp.async.commit_group;" ::: "memory")
#define CP_WAIT(n)  asm volatile("cp.async.wait_group %0;" :: "n"(n) : "memory")

__device__ __forceinline__ float red32(float v) {
    #pragma unroll
    for (int o = 16; o > 0; o >>= 1)
        v += __shfl_xor_sync(0xffffffffu, v, o);
    return v;
}

// ---------------- fused prep -------------------------------------------------
#define PREP_WBLOCKS 360
#define PREP_XBLOCKS 4608
__global__ void __launch_bounds__(256) k_prepall(
    const float* __restrict__ W, const float* __restrict__ X) {
    int tid = threadIdx.x;
    if (blockIdx.x < PREP_WBLOCKS) {
        __shared__ float ts[256][20];      // [pd_local][t]
        int tb = blockIdx.x;
        int n  = tb / 36;
        int pd0 = (tb % 36) * 256;
        int p0 = pd0 >> 3;

        int z = tb*256 + tid;
        if (z < P*NCAPS) { g_b[z] = 0.0f; g_bbar[z] = 0.0f; }
        if (z < BATCH*NT/4)
            ((float4*)g_s)[z] = make_float4(0.0f, 0.0f, 0.0f, 0.0f);

        {   // read W: 32 p-chunks x 128 contiguous floats, float4
            int chunk = tid >> 3, inner = tid & 7;
            const float* src = W + (size_t)(p0 + chunk)*(NCAPS*T*D) + n*(T*D)
                               + inner*16;
            #pragma unroll
            for (int j4 = 0; j4 < 4; ++j4) {
                float4 v = *(const float4*)(src + j4*4);
                int l0 = inner*16 + j4*4;
                int t = l0 >> 3, d = l0 & 7;
                ts[chunk*8 + d    ][t] = v.x;
                ts[chunk*8 + d + 1][t] = v.y;
                ts[chunk*8 + d + 2][t] = v.z;
                ts[chunk*8 + d + 3][t] = v.w;
            }
        }
        __syncthreads();
        {   // Wt2h [pd][nt]: 8B stores
            int lane4 = tid & 3, rbase = tid >> 2;
            #pragma unroll
            for (int rr = 0; rr < 4; ++rr) {
                int row = rbase + rr*64;
                float4 v = *(const float4*)&ts[row][lane4*4];
                __half2 ha = __floats2half2_rn(v.x, v.y);
                __half2 hb = __floats2half2_rn(v.z, v.w);
                uint2 u2;
                u2.x = *(uint32_t*)&ha; u2.y = *(uint32_t*)&hb;
                *(uint2*)&g_Wt2h[(size_t)(pd0 + row)*NT + n*16 + lane4*4] = u2;
            }
        }
        {   // Bq [nt][pd]: 32B (sector-exact) per thread
            int ntl = tid & 15, pdl = (tid >> 4) * 16;
            __half hbuf[16];
            #pragma unroll
            for (int j = 0; j < 16; ++j)
                hbuf[j] = __float2half_rn(0.1f * ts[pdl + j][ntl]);
            uint4* dst = (uint4*)&g_Bq[(size_t)(n*16 + ntl)*PD + pd0 + pdl];
            dst[0] = *(uint4*)&hbuf[0];
            dst[1] = *(uint4*)&hbuf[8];
        }
    } else {
        __shared__ __half tb2[32][33];
        int bid = blockIdx.x - PREP_WBLOCKS;
        int pd0 = (bid % (PD/32)) * 32, b0 = (bid / (PD/32)) * 32;
        int tx = tid & 31, ty = tid >> 5;
        #pragma unroll
        for (int j = 0; j < 32; j += 8) {
            float v = X[(size_t)(b0 + ty + j)*PD + pd0 + tx];
            __half h = __float2half_rn(v);
            g_Xq[(size_t)(b0 + ty + j)*PD + pd0 + tx] = h;
            tb2[ty + j][tx] = h;
        }
        __syncthreads();
        #pragma unroll
        for (int j = 0; j < 32; j += 8)
            g_Xtq[(size_t)(pd0 + ty + j)*BATCH + b0 + tx] = tb2[tx][ty + j];
    }
}

// ---------------- compute one K=32 stage -------------------------------------
__device__ __forceinline__ void compute_stage(
    uint32_t base, int wm32, int wn40, int lane, float acc[2][5][4]) {
    int grp = lane >> 3, lr = lane & 7;
    #pragma unroll
    for (int ko = 0; ko < 32; ko += 16) {
        uint32_t bh[5][2];
        #pragma unroll
        for (int bp = 0; bp < 2; ++bp) {
            uint32_t ba = (uint32_t)((wn40 + bp*16 + ((grp & 2) << 2) + lr)*SROW
                                     + (ko + (grp & 1)*8)*2);
            uint32_t r4[4];
            ldmx4(r4, base + B_OFF + ba);
            bh[bp*2][0]   = r4[0]; bh[bp*2][1]   = r4[1];
            bh[bp*2+1][0] = r4[2]; bh[bp*2+1][1] = r4[3];
        }
        {
            uint32_t ba = (uint32_t)((wn40 + 32 + lr)*SROW + (ko + (grp & 1)*8)*2);
            ldmx2(bh[4], base + B_OFF + ba);
        }
        #pragma unroll
        for (int mt = 0; mt < 2; ++mt) {
            uint32_t aa = (uint32_t)((wm32 + mt*16 + (grp & 1)*8 + lr)*SROW
                                     + (ko + (grp >> 1)*8)*2);
            uint32_t ah[4];
            ldmx4(ah, base + aa);
            #pragma unroll
            for (int bt = 0; bt < 5; ++bt)
                mma16816(acc[mt][bt], ah[0], ah[1], ah[2], ah[3], bh[bt][0], bh[bt][1]);
        }
    }
}

// ---------------- GEMM1 + fused squash tail ----------------------------------
// g_s[b][nt] += X[64b x 256k] * Bq[256k x 160]; last chunk-block per b-tile
// does the squash for its 64 rows (replaces k_redsquash).
__global__ void __launch_bounds__(256, 2) k_gemm1(float* __restrict__ out,
                                                  int final_it) {
    extern __shared__ char smem[];
    __shared__ int amlast;
    uint32_t sb = s2u(smem);
    int tid = threadIdx.x;
    int wid = tid >> 5, lane = tid & 31;
    int wm32 = (wid >> 2) * 32;
    int wn40 = (wid & 3) * 40;
    int b0 = blockIdx.x * 64;
    int kc = blockIdx.y * 256;

    float acc[2][5][4];
    #pragma unroll
    for (int i = 0; i < 2; ++i)
        #pragma unroll
        for (int j = 0; j < 5; ++j)
            #pragma unroll
            for (int r = 0; r < 4; ++r) acc[i][j][r] = 0.0f;

    auto issue = [&](int s, int buf) {
        int kb = kc + s*32;
        uint32_t base = sb + buf*STAGE_BYTES;
        {   // A: 64 rows x 4 chunks = 256, 1/thread
            int row = tid >> 2, q = tid & 3;
            cpasync16(base + row*SROW + q*16,
                      g_Xq + (size_t)(b0 + row)*PD + kb + q*8);
        }
        #pragma unroll
        for (int u = 0; u < 3; ++u) {   // B: 160 rows x 4 = 640
            int ch = tid + 256*u;
            if (ch < 640) {
                int row = ch >> 2, q = ch & 3;
                cpasync16(base + B_OFF + row*SROW + q*16,
                          g_Bq + (size_t)row*PD + kb + q*8);
            }
        }
    };

    issue(0, 0); CP_COMMIT();
    issue(1, 1); CP_COMMIT();
    issue(2, 2); CP_COMMIT();
    #pragma unroll 1
    for (int s = 0; s < 8; ++s) {
        CP_WAIT(2);
        __syncthreads();
        if (s + 3 < 8) issue(s + 3, (s + 3) & 3);
        CP_COMMIT();
        compute_stage(sb + (s & 3)*STAGE_BYTES, wm32, wn40, lane, acc);
    }

    int g = lane >> 2, qq = (lane & 3)*2;
    #pragma unroll
    for (int mt = 0; mt < 2; ++mt) {
        int row = b0 + wm32 + mt*16 + g;
        #pragma unroll
        for (int bt = 0; bt < 5; ++bt) {
            int col = wn40 + bt*8 + qq;
            atomicAdd(&g_s[(size_t)row*NT + col],       acc[mt][bt][0]);
            atomicAdd(&g_s[(size_t)row*NT + col + 1],   acc[mt][bt][1]);
            atomicAdd(&g_s[(size_t)(row+8)*NT + col],   acc[mt][bt][2]);
            atomicAdd(&g_s[(size_t)(row+8)*NT + col+1], acc[mt][bt][3]);
        }
    }

    // -------- last-arriving chunk-block does the squash for this b-tile ------
    __threadfence();
    if (tid == 0) {
        int old = atomicAdd(&g_cnt1[blockIdx.x], 1);
        amlast = (old == KCH1 - 1);
        if (amlast) g_cnt1[blockIdx.x] = 0;      // self-reset for next launch
    }
    __syncthreads();
    if (!amlast) return;
    __threadfence();

    // 64 rows x 40 float4 = 2560 units; aligned 4-lane groups share one (b,n)
    #pragma unroll
    for (int u = 0; u < 10; ++u) {
        int fl = tid + 256*u;
        int row = fl / 40, c4 = fl % 40;
        int b = b0 + row;
        float4 s = __ldcg((const float4*)&g_s[(size_t)b*NT + c4*4]);
        float ss = s.x*s.x + s.y*s.y + s.z*s.z + s.w*s.w;
        ss += __shfl_xor_sync(0xffffffffu, ss, 1);
        ss += __shfl_xor_sync(0xffffffffu, ss, 2);
        float nrm = sqrtf(ss);
        float f = ss / (1.0f + ss*(nrm + 1e-9f));
        float4 v = make_float4(f*s.x, f*s.y, f*s.z, f*s.w);
        if (final_it) {
            *(float4*)&out[(size_t)b*NT + c4*4] = v;
        } else {
            *(float4*)&g_s[(size_t)b*NT + c4*4] = make_float4(0.f, 0.f, 0.f, 0.f);
            int nt = c4*4;
            g_vq[(size_t)nt*BATCH + b]     = __float2half_rn(v.x);
            g_vq[(size_t)(nt+1)*BATCH + b] = __float2half_rn(v.y);
            g_vq[(size_t)(nt+2)*BATCH + b] = __float2half_rn(v.z);
            g_vq[(size_t)(nt+3)*BATCH + b] = __float2half_rn(v.w);
        }
    }
}

// ---------------- GEMM2 + agreement + fused route/splitB tail ----------------
__global__ void __launch_bounds__(256, 2) k_gemm2(const float* __restrict__ W) {
    extern __shared__ char smem[];
    __shared__ int amlast;
    __shared__ float sbn[8][10];
    __shared__ float sc[8][10];
    uint32_t sb = s2u(smem);
    int tid = threadIdx.x;
    int wid = tid >> 5, lane = tid & 31;
    int wm32 = (wid >> 2) * 32;
    int wn40 = (wid & 3) * 40;
    int pd0 = blockIdx.x * 64;
    int kc = blockIdx.y * 256;

    float acc[2][5][4];
    #pragma unroll
    for (int i = 0; i < 2; ++i)
        #pragma unroll
        for (int j = 0; j < 5; ++j)
            #pragma unroll
            for (int r = 0; r < 4; ++r) acc[i][j][r] = 0.0f;

    auto issue = [&](int s, int buf) {
        int kb = kc + s*32;
        uint32_t base = sb + buf*STAGE_BYTES;
        {
            int row = tid >> 2, q = tid & 3;
            cpasync16(base + row*SROW + q*16,
                      g_Xtq + (size_t)(pd0 + row)*BATCH + kb + q*8);
        }
        #pragma unroll
        for (int u = 0; u < 3; ++u) {
            int ch = tid + 256*u;
            if (ch < 640) {
                int row = ch >> 2, q = ch & 3;
                cpasync16(base + B_OFF + row*SROW + q*16,
                          g_vq + (size_t)row*BATCH + kb + q*8);
            }
        }
    };
    auto issue_wt2 = [&](int part) {
        if (part == 0) {
            #pragma unroll
            for (int u = 0; u < 5; ++u) {
                int ch = tid + 256*u;
                if (ch < 1120) {
                    int row = ch / 20, c = ch % 20;
                    cpasync16(sb + ch*16,
                              g_Wt2h + (size_t)(pd0 + row)*NT + c*8);
                }
            }
        } else if (part == 1) {
            if (tid < 160) {
                int ch = 1120 + tid;
                int row = ch / 20, c = ch % 20;
                cpasync16(sb + ch*16,
                          g_Wt2h + (size_t)(pd0 + row)*NT + c*8);
            }
        }
    };

    issue(0, 0); CP_COMMIT();
    issue(1, 1); CP_COMMIT();
    issue(2, 2); CP_COMMIT();
    #pragma unroll 1
    for (int s = 0; s < 8; ++s) {
        CP_WAIT(2);
        __syncthreads();
        if (s + 3 < 8) issue(s + 3, (s + 3) & 3);
        else           issue_wt2(s - 5);
        CP_COMMIT();
        compute_stage(sb + (s & 3)*STAGE_BYTES, wm32, wn40, lane, acc);
    }
    CP_WAIT(0);
    __syncthreads();

    const __half* wth = (const __half*)smem;   // Wt2h tile [64][160]
    int g = lane >> 2, qq = (lane & 3)*2;
    #pragma unroll
    for (int mt = 0; mt < 2; ++mt) {
        int r0 = wm32 + mt*16 + g;
        int pg = (pd0 + wm32 + mt*16) >> 3;
        float v0 = 0.0f, v1 = 0.0f;
        int curn = wn40 >> 4;
        #pragma unroll
        for (int bt = 0; bt < 5; ++bt) {
            int colb = wn40 + bt*8;
            int n = colb >> 4;
            if (n != curn) {                     // warp-uniform branch
                float s0 = red32(v0), s1 = red32(v1);
                if (lane == 0) {
                    atomicAdd(&g_bbar[pg*NCAPS + curn], s0);
                    atomicAdd(&g_bbar[(pg + 1)*NCAPS + curn], s1);
                }
                v0 = v1 = 0.0f;
                curn = n;
            }
            int col = colb + qq;
            float2 w0 = __half22float2(*(const __half2*)&wth[r0*NT + col]);
            float2 w1 = __half22float2(*(const __half2*)&wth[(r0 + 8)*NT + col]);
            v0 += acc[mt][bt][0]*w0.x + acc[mt][bt][1]*w0.y;
            v1 += acc[mt][bt][2]*w1.x + acc[mt][bt][3]*w1.y;
        }
        {
            float s0 = red32(v0), s1 = red32(v1);
            if (lane == 0) {
                atomicAdd(&g_bbar[pg*NCAPS + curn], s0);
                atomicAdd(&g_bbar[(pg + 1)*NCAPS + curn], s1);
            }
        }
    }

    // -------- last-arriving chunk-block does route + splitB for this pd-tile -
    __threadfence();
    if (tid == 0) {
        int old = atomicAdd(&g_cnt2[blockIdx.x], 1);
        amlast = (old == KCH2 - 1);
        if (amlast) g_cnt2[blockIdx.x] = 0;
    }
    __syncthreads();
    if (!amlast) return;
    __threadfence();

    int p0 = pd0 >> 3;
    if (tid < 80) {
        int lp = tid / 10, n = tid - lp*10;
        int p = p0 + lp;
        float bn = g_b[p*NCAPS + n]
                 + __ldcg(&g_bbar[p*NCAPS + n]) * (1.0f / (float)BATCH);
        g_b[p*NCAPS + n] = bn;
        g_bbar[p*NCAPS + n] = 0.0f;              // zero for next iteration
        sbn[lp][n] = bn;
    }
    __syncthreads();
    if (tid < 8) {
        float mx = -1e30f;
        #pragma unroll
        for (int n = 0; n < NCAPS; ++n) mx = fmaxf(mx, sbn[tid][n]);
        float sum = 0.0f;
        float e[NCAPS];
        #pragma unroll
        for (int n = 0; n < NCAPS; ++n) { e[n] = expf(sbn[tid][n] - mx); sum += e[n]; }
        float rs = 1.0f / sum;
        #pragma unroll
        for (int n = 0; n < NCAPS; ++n) sc[tid][n] = e[n]*rs;
    }
    __syncthreads();

    #pragma unroll
    for (int u = 0; u < 10; ++u) {
        int fl = tid + 256*u;          // 0..2559: 160 nt x 16 pd-quads
        int nt = fl >> 4, pdq = fl & 15;
        int n = nt >> 4, t = nt & 15;
        int p = p0 + (pdq >> 1), d0 = (pdq & 1)*4;
        float c = sc[pdq >> 1][n];
        float4 w = *(const float4*)&W[((p*NCAPS + n)*T + t)*D + d0];
        size_t base = (size_t)nt*PD + pd0 + pdq*4;
        *(__half2*)&g_Bq[base]     = __floats2half2_rn(w.x*c, w.y*c);
        *(__half2*)&g_Bq[base + 2] = __floats2half2_rn(w.z*c, w.w*c);
    }
}

// ---------------- launch -----------------------------------------------------
extern "C" void kernel_launch(void* const* d_in, const int* in_sizes, int n_in,
                              void* d_out, int out_size) {
    (void)in_sizes; (void)n_in; (void)out_size;
    const float* x = (const float*)d_in[0];   // [512, 1152, 8]
    const float* W = (const float*)d_in[1];   // [1152, 10, 16, 8]
    float* out = (float*)d_out;               // [512, 10, 16, 1]

    cudaFuncSetAttribute((const void*)k_gemm1,
                         cudaFuncAttributeMaxDynamicSharedMemorySize, SMEM_BYTES);
    cudaFuncSetAttribute((const void*)k_gemm2,
                         cudaFuncAttributeMaxDynamicSharedMemorySize, SMEM_BYTES);

    k_prepall<<<PREP_WBLOCKS + PREP_XBLOCKS, 256>>>(W, x);

    for (int it = 0; it < 3; ++it) {
        k_gemm1<<<dim3(BATCH/64, KCH1), 256, SMEM_BYTES>>>(out, it == 2 ? 1 : 0);
        if (it < 2)
            k_gemm2<<<dim3(PD/64, KCH2), 256, SMEM_BYTES>>>(W);
    }
}

// round 16
// speedup vs baseline: 1.5130x; 1.5130x over previous
#include <cuda_runtime.h>
#include <cuda_fp16.h>
#include <math.h>
#include <stdint.h>

#define BATCH 512
#define P 1152
#define NCAPS 10
#define T 16
#define D 8
#define PD 9216          // P*D
#define NT 160           // NCAPS*T
#define KCH1 36          // split-K chunks gemm1 (36*256 = 9216)
#define KCH2 2           // split-K chunks gemm2 (2*256 = 512)

// SMEM stage: K=32 halves (64B/row), 80B row stride.
#define SROW 80
#define B_OFF   5120             // 64*80
#define STAGE_BYTES 17920        // + 160*80
#define NSTAGE 4
#define SMEM_BYTES (NSTAGE*STAGE_BYTES)   // 71680 -> 2 CTAs/SM

// ---------------- scratch ----------------------------------------------------
__device__ __half g_Wt2h[PD*NT];      // fl16(W) [pd][nt] (gemm2 epilogue)
__device__ __half g_Xq[BATCH*PD];     // fl16(X) [b][pd]
__device__ __half g_Xtq[PD*BATCH];    // fl16(X)^T [pd][b]
__device__ __half g_Bq[NT*PD];        // fl16(c.W) [nt][pd]
__device__ __half g_vq[NT*BATCH];     // fl16(v) [nt][b]
__device__ float  g_s[BATCH*NT];      // atomically-accumulated s [b][nt]
__device__ float  g_bbar[P*NCAPS];
__device__ float  g_b[P*NCAPS];

// ---------------- PTX helpers ------------------------------------------------
__device__ __forceinline__ void mma16816(float* c,
    uint32_t a0, uint32_t a1, uint32_t a2, uint32_t a3,
    uint32_t b0, uint32_t b1) {
    asm volatile(
        "mma.sync.aligned.m16n8k16.row.col.f32.f16.f16.f32 "
        "{%0,%1,%2,%3}, {%4,%5,%6,%7}, {%8,%9}, {%0,%1,%2,%3};"
        : "+f"(c[0]), "+f"(c[1]), "+f"(c[2]), "+f"(c[3])
        : "r"(a0), "r"(a1), "r"(a2), "r"(a3), "r"(b0), "r"(b1));
}
__device__ __forceinline__ void ldmx4(uint32_t* r, uint32_t addr) {
    asm volatile("ldmatrix.sync.aligned.m8n8.x4.shared.b16 {%0,%1,%2,%3}, [%4];"
        : "=r"(r[0]), "=r"(r[1]), "=r"(r[2]), "=r"(r[3]) : "r"(addr));
}
__device__ __forceinline__ void ldmx2(uint32_t* r, uint32_t addr) {
    asm volatile("ldmatrix.sync.aligned.m8n8.x2.shared.b16 {%0,%1}, [%2];"
        : "=r"(r[0]), "=r"(r[1]) : "r"(addr));
}
__device__ __forceinline__ uint32_t s2u(const void* p) {
    uint32_t a;
    asm("{ .reg .u64 t; cvta.to.shared.u64 t, %1; cvt.u32.u64 %0, t; }"
        : "=r"(a) : "l"(p));
    return a;
}
__device__ __forceinline__ void cpasync16(uint32_t dst, const void* src) {
    asm volatile("cp.async.cg.shared.global [%0], [%1], 16;"
        :: "r"(dst), "l"(__cvta_generic_to_global(src)));
}
#define CP_COMMIT() asm volatile("cp.async.commit_group;" ::: "memory")
#define CP_WAIT(n)  asm volatile("cp.async.wait_group %0;" :: "n"(n) : "memory")

__device__ __forceinline__ void redg2(float* p, float a, float b) {
    asm volatile("red.global.add.v2.f32 [%0], {%1, %2};"
        :: "l"(__cvta_generic_to_global(p)), "f"(a), "f"(b) : "memory");
}
__device__ __forceinline__ float red32(float v) {
    #pragma unroll
    for (int o = 16; o > 0; o >>= 1)
        v += __shfl_xor_sync(0xffffffffu, v, o);
    return v;
}

// ---------------- fused prep -------------------------------------------------
#define PREP_WBLOCKS 360
#define PREP_XBLOCKS 4608
__global__ void __launch_bounds__(256) k_prepall(
    const float* __restrict__ W, const float* __restrict__ X) {
    int tid = threadIdx.x;
    if (blockIdx.x < PREP_WBLOCKS) {
        __shared__ float ts[256][20];      // [pd_local][t]
        int tb = blockIdx.x;
        int n  = tb / 36;
        int pd0 = (tb % 36) * 256;
        int p0 = pd0 >> 3;

        int z = tb*256 + tid;
        if (z < P*NCAPS) g_b[z] = 0.0f;
        if (z < BATCH*NT/4)
            ((float4*)g_s)[z] = make_float4(0.0f, 0.0f, 0.0f, 0.0f);

        {   // read W: 32 p-chunks x 128 contiguous floats, float4
            int chunk = tid >> 3, inner = tid & 7;
            const float* src = W + (size_t)(p0 + chunk)*(NCAPS*T*D) + n*(T*D)
                               + inner*16;
            #pragma unroll
            for (int j4 = 0; j4 < 4; ++j4) {
                float4 v = *(const float4*)(src + j4*4);
                int l0 = inner*16 + j4*4;
                int t = l0 >> 3, d = l0 & 7;
                ts[chunk*8 + d    ][t] = v.x;
                ts[chunk*8 + d + 1][t] = v.y;
                ts[chunk*8 + d + 2][t] = v.z;
                ts[chunk*8 + d + 3][t] = v.w;
            }
        }
        __syncthreads();
        {   // Wt2h [pd][nt]: 8B stores
            int lane4 = tid & 3, rbase = tid >> 2;
            #pragma unroll
            for (int rr = 0; rr < 4; ++rr) {
                int row = rbase + rr*64;
                float4 v = *(const float4*)&ts[row][lane4*4];
                __half2 ha = __floats2half2_rn(v.x, v.y);
                __half2 hb = __floats2half2_rn(v.z, v.w);
                uint2 u2;
                u2.x = *(uint32_t*)&ha; u2.y = *(uint32_t*)&hb;
                *(uint2*)&g_Wt2h[(size_t)(pd0 + row)*NT + n*16 + lane4*4] = u2;
            }
        }
        {   // Bq [nt][pd]: 32B (sector-exact) per thread
            int ntl = tid & 15, pdl = (tid >> 4) * 16;
            __half hbuf[16];
            #pragma unroll
            for (int j = 0; j < 16; ++j)
                hbuf[j] = __float2half_rn(0.1f * ts[pdl + j][ntl]);
            uint4* dst = (uint4*)&g_Bq[(size_t)(n*16 + ntl)*PD + pd0 + pdl];
            dst[0] = *(uint4*)&hbuf[0];
            dst[1] = *(uint4*)&hbuf[8];
        }
    } else {
        __shared__ __half tb2[32][33];
        int bid = blockIdx.x - PREP_WBLOCKS;
        int pd0 = (bid % (PD/32)) * 32, b0 = (bid / (PD/32)) * 32;
        int tx = tid & 31, ty = tid >> 5;
        #pragma unroll
        for (int j = 0; j < 32; j += 8) {
            float v = X[(size_t)(b0 + ty + j)*PD + pd0 + tx];
            __half h = __float2half_rn(v);
            g_Xq[(size_t)(b0 + ty + j)*PD + pd0 + tx] = h;
            tb2[ty + j][tx] = h;
        }
        __syncthreads();
        #pragma unroll
        for (int j = 0; j < 32; j += 8)
            g_Xtq[(size_t)(pd0 + ty + j)*BATCH + b0 + tx] = tb2[tx][ty + j];
    }
}

// ---------------- compute one K=32 stage -------------------------------------
__device__ __forceinline__ void compute_stage(
    uint32_t base, int wm32, int wn40, int lane, float acc[2][5][4]) {
    int grp = lane >> 3, lr = lane & 7;
    #pragma unroll
    for (int ko = 0; ko < 32; ko += 16) {
        uint32_t bh[5][2];
        #pragma unroll
        for (int bp = 0; bp < 2; ++bp) {
            uint32_t ba = (uint32_t)((wn40 + bp*16 + ((grp & 2) << 2) + lr)*SROW
                                     + (ko + (grp & 1)*8)*2);
            uint32_t r4[4];
            ldmx4(r4, base + B_OFF + ba);
            bh[bp*2][0]   = r4[0]; bh[bp*2][1]   = r4[1];
            bh[bp*2+1][0] = r4[2]; bh[bp*2+1][1] = r4[3];
        }
        {
            uint32_t ba = (uint32_t)((wn40 + 32 + lr)*SROW + (ko + (grp & 1)*8)*2);
            ldmx2(bh[4], base + B_OFF + ba);
        }
        #pragma unroll
        for (int mt = 0; mt < 2; ++mt) {
            uint32_t aa = (uint32_t)((wm32 + mt*16 + (grp & 1)*8 + lr)*SROW
                                     + (ko + (grp >> 1)*8)*2);
            uint32_t ah[4];
            ldmx4(ah, base + aa);
            #pragma unroll
            for (int bt = 0; bt < 5; ++bt)
                mma16816(acc[mt][bt], ah[0], ah[1], ah[2], ah[3], bh[bt][0], bh[bt][1]);
        }
    }
}

// ---------------- GEMM1: g_s[b][nt] += X[64b x 256k] * Bq[256k x 160] --------
__global__ void __launch_bounds__(256, 2) k_gemm1() {
    extern __shared__ char smem[];
    uint32_t sb = s2u(smem);
    int tid = threadIdx.x;
    int wid = tid >> 5, lane = tid & 31;
    int wm32 = (wid >> 2) * 32;
    int wn40 = (wid & 3) * 40;
    int b0 = blockIdx.x * 64;
    int kc = blockIdx.y * 256;

    float acc[2][5][4];
    #pragma unroll
    for (int i = 0; i < 2; ++i)
        #pragma unroll
        for (int j = 0; j < 5; ++j)
            #pragma unroll
            for (int r = 0; r < 4; ++r) acc[i][j][r] = 0.0f;

    auto issue = [&](int s, int buf) {
        int kb = kc + s*32;
        uint32_t base = sb + buf*STAGE_BYTES;
        {   // A: 64 rows x 4 chunks = 256, 1/thread
            int row = tid >> 2, q = tid & 3;
            cpasync16(base + row*SROW + q*16,
                      g_Xq + (size_t)(b0 + row)*PD + kb + q*8);
        }
        #pragma unroll
        for (int u = 0; u < 3; ++u) {   // B: 160 rows x 4 = 640
            int ch = tid + 256*u;
            if (ch < 640) {
                int row = ch >> 2, q = ch & 3;
                cpasync16(base + B_OFF + row*SROW + q*16,
                          g_Bq + (size_t)row*PD + kb + q*8);
            }
        }
    };

    issue(0, 0); CP_COMMIT();
    issue(1, 1); CP_COMMIT();
    issue(2, 2); CP_COMMIT();
    #pragma unroll 1
    for (int s = 0; s < 8; ++s) {
        CP_WAIT(2);
        __syncthreads();
        if (s + 3 < 8) issue(s + 3, (s + 3) & 3);
        CP_COMMIT();
        compute_stage(sb + (s & 3)*STAGE_BYTES, wm32, wn40, lane, acc);
    }

    int g = lane >> 2, qq = (lane & 3)*2;
    #pragma unroll
    for (int mt = 0; mt < 2; ++mt) {
        int row = b0 + wm32 + mt*16 + g;
        #pragma unroll
        for (int bt = 0; bt < 5; ++bt) {
            int col = wn40 + bt*8 + qq;
            redg2(&g_s[(size_t)row*NT + col],     acc[mt][bt][0], acc[mt][bt][1]);
            redg2(&g_s[(size_t)(row+8)*NT + col], acc[mt][bt][2], acc[mt][bt][3]);
        }
    }
}

// ---------------- GEMM2 + fused agreement epilogue ---------------------------
// Wt2h tile (64 x 160 fp16 = 20480B) prefetched into retired stage bufs 0-1.
__global__ void __launch_bounds__(256, 2) k_gemm2() {
    extern __shared__ char smem[];
    uint32_t sb = s2u(smem);
    int tid = threadIdx.x;
    int wid = tid >> 5, lane = tid & 31;
    int wm32 = (wid >> 2) * 32;
    int wn40 = (wid & 3) * 40;
    int pd0 = blockIdx.x * 64;
    int kc = blockIdx.y * 256;

    float acc[2][5][4];
    #pragma unroll
    for (int i = 0; i < 2; ++i)
        #pragma unroll
        for (int j = 0; j < 5; ++j)
            #pragma unroll
            for (int r = 0; r < 4; ++r) acc[i][j][r] = 0.0f;

    auto issue = [&](int s, int buf) {
        int kb = kc + s*32;
        uint32_t base = sb + buf*STAGE_BYTES;
        {
            int row = tid >> 2, q = tid & 3;
            cpasync16(base + row*SROW + q*16,
                      g_Xtq + (size_t)(pd0 + row)*BATCH + kb + q*8);
        }
        #pragma unroll
        for (int u = 0; u < 3; ++u) {
            int ch = tid + 256*u;
            if (ch < 640) {
                int row = ch >> 2, q = ch & 3;
                cpasync16(base + B_OFF + row*SROW + q*16,
                          g_vq + (size_t)row*BATCH + kb + q*8);
            }
        }
    };
    auto issue_wt2 = [&](int part) {
        if (part == 0) {
            #pragma unroll
            for (int u = 0; u < 5; ++u) {
                int ch = tid + 256*u;
                if (ch < 1120) {
                    int row = ch / 20, c = ch % 20;
                    cpasync16(sb + ch*16,
                              g_Wt2h + (size_t)(pd0 + row)*NT + c*8);
                }
            }
        } else if (part == 1) {
            if (tid < 160) {
                int ch = 1120 + tid;
                int row = ch / 20, c = ch % 20;
                cpasync16(sb + ch*16,
                          g_Wt2h + (size_t)(pd0 + row)*NT + c*8);
            }
        }
    };

    issue(0, 0); CP_COMMIT();
    issue(1, 1); CP_COMMIT();
    issue(2, 2); CP_COMMIT();
    #pragma unroll 1
    for (int s = 0; s < 8; ++s) {
        CP_WAIT(2);
        __syncthreads();
        if (s + 3 < 8) issue(s + 3, (s + 3) & 3);
        else           issue_wt2(s - 5);
        CP_COMMIT();
        compute_stage(sb + (s & 3)*STAGE_BYTES, wm32, wn40, lane, acc);
    }
    CP_WAIT(0);
    __syncthreads();

    const __half* wth = (const __half*)smem;   // Wt2h tile [64][160]
    int g = lane >> 2, qq = (lane & 3)*2;
    #pragma unroll
    for (int mt = 0; mt < 2; ++mt) {
        int r0 = wm32 + mt*16 + g;
        int pg = (pd0 + wm32 + mt*16) >> 3;
        float v0 = 0.0f, v1 = 0.0f;
        int curn = wn40 >> 4;
        #pragma unroll
        for (int bt = 0; bt < 5; ++bt) {
            int colb = wn40 + bt*8;
            int n = colb >> 4;
            if (n != curn) {                     // warp-uniform branch
                float s0 = red32(v0), s1 = red32(v1);
                if (lane == 0) {
                    atomicAdd(&g_bbar[pg*NCAPS + curn], s0);
                    atomicAdd(&g_bbar[(pg + 1)*NCAPS + curn], s1);
                }
                v0 = v1 = 0.0f;
                curn = n;
            }
            int col = colb + qq;
            float2 w0 = __half22float2(*(const __half2*)&wth[r0*NT + col]);
            float2 w1 = __half22float2(*(const __half2*)&wth[(r0 + 8)*NT + col]);
            v0 += acc[mt][bt][0]*w0.x + acc[mt][bt][1]*w0.y;
            v1 += acc[mt][bt][2]*w1.x + acc[mt][bt][3]*w1.y;
        }
        {
            float s0 = red32(v0), s1 = red32(v1);
            if (lane == 0) {
                atomicAdd(&g_bbar[pg*NCAPS + curn], s0);
                atomicAdd(&g_bbar[(pg + 1)*NCAPS + curn], s1);
            }
        }
    }
}

// ---------------- squash (reads g_s, zeroes it for next iter) ----------------
__global__ void k_redsquash(float* __restrict__ out, int final_it) {
    int i4 = blockIdx.x * blockDim.x + threadIdx.x;   // [0, BATCH*NT/4)
    float4 s = ((const float4*)g_s)[i4];
    float ss = s.x*s.x + s.y*s.y + s.z*s.z + s.w*s.w;
    #pragma unroll
    for (int o = 1; o < 4; o <<= 1)
        ss += __shfl_xor_sync(0xffffffffu, ss, o);    // 4 lanes x 4 = 16 t's
    float nrm = sqrtf(ss);
    float f = ss / (1.0f + ss*(nrm + 1e-9f));
    float4 v = make_float4(f*s.x, f*s.y, f*s.z, f*s.w);
    if (final_it) {
        ((float4*)out)[i4] = v;
    } else {
        ((float4*)g_s)[i4] = make_float4(0.0f, 0.0f, 0.0f, 0.0f);
        int idx = 4*i4;
        int b = idx / NT, nt = idx - b*NT;
        g_vq[(size_t)nt*BATCH + b]     = __float2half_rn(v.x);
        g_vq[(size_t)(nt+1)*BATCH + b] = __float2half_rn(v.y);
        g_vq[(size_t)(nt+2)*BATCH + b] = __float2half_rn(v.z);
        g_vq[(size_t)(nt+3)*BATCH + b] = __float2half_rn(v.w);
        if (i4 < P*NCAPS/4)
            ((float4*)g_bbar)[i4] = make_float4(0.0f, 0.0f, 0.0f, 0.0f);
    }
}

// ---------------- fused route (softmax) + B quantize -------------------------
__global__ void __launch_bounds__(256) k_routesplitB(const float* __restrict__ W) {
    __shared__ float sbn[8][10];
    __shared__ float sc[8][10];
    int tid = threadIdx.x;
    int p0 = blockIdx.x * 8;
    int pd0 = blockIdx.x * 64;

    if (tid < 80) {
        int lp = tid / 10, n = tid - lp*10;
        int p = p0 + lp;
        float bn = g_b[p*NCAPS + n] + g_bbar[p*NCAPS + n] * (1.0f / (float)BATCH);
        g_b[p*NCAPS + n] = bn;
        sbn[lp][n] = bn;
    }
    __syncthreads();
    if (tid < 8) {
        float mx = -1e30f;
        #pragma unroll
        for (int n = 0; n < NCAPS; ++n) mx = fmaxf(mx, sbn[tid][n]);
        float sum = 0.0f;
        float e[NCAPS];
        #pragma unroll
        for (int n = 0; n < NCAPS; ++n) { e[n] = expf(sbn[tid][n] - mx); sum += e[n]; }
        float rs = 1.0f / sum;
        #pragma unroll
        for (int n = 0; n < NCAPS; ++n) sc[tid][n] = e[n]*rs;
    }
    __syncthreads();

    #pragma unroll
    for (int u = 0; u < 10; ++u) {
        int fl = tid + 256*u;          // 0..2559: 160 nt x 16 pd-quads
        int nt = fl >> 4, pdq = fl & 15;
        int n = nt >> 4, t = nt & 15;
        int p = p0 + (pdq >> 1), d0 = (pdq & 1)*4;
        float c = sc[pdq >> 1][n];
        float4 w = *(const float4*)&W[((p*NCAPS + n)*T + t)*D + d0];
        size_t base = (size_t)nt*PD + pd0 + pdq*4;
        *(__half2*)&g_Bq[base]     = __floats2half2_rn(w.x*c, w.y*c);
        *(__half2*)&g_Bq[base + 2] = __floats2half2_rn(w.z*c, w.w*c);
    }
}

// ---------------- launch -----------------------------------------------------
extern "C" void kernel_launch(void* const* d_in, const int* in_sizes, int n_in,
                              void* d_out, int out_size) {
    (void)in_sizes; (void)n_in; (void)out_size;
    const float* x = (const float*)d_in[0];   // [512, 1152, 8]
    const float* W = (const float*)d_in[1];   // [1152, 10, 16, 8]
    float* out = (float*)d_out;               // [512, 10, 16, 1]

    cudaFuncSetAttribute((const void*)k_gemm1,
                         cudaFuncAttributeMaxDynamicSharedMemorySize, SMEM_BYTES);
    cudaFuncSetAttribute((const void*)k_gemm2,
                         cudaFuncAttributeMaxDynamicSharedMemorySize, SMEM_BYTES);

    k_prepall<<<PREP_WBLOCKS + PREP_XBLOCKS, 256>>>(W, x);

    for (int it = 0; it < 3; ++it) {
        k_gemm1<<<dim3(BATCH/64, KCH1), 256, SMEM_BYTES>>>();
        k_redsquash<<<(BATCH*NT/4)/128, 128>>>(out, it == 2 ? 1 : 0);
        if (it < 2) {
            k_gemm2<<<dim3(PD/64, KCH2), 256, SMEM_BYTES>>>();
            k_routesplitB<<<P/8, 256>>>(W);
        }
    }
}

// round 17
// speedup vs baseline: 1.5594x; 1.0307x over previous
#include <cuda_runtime.h>
#include <cuda_fp16.h>
#include <math.h>
#include <stdint.h>

#define BATCH 512
#define P 1152
#define NCAPS 10
#define T 16
#define D 8
#define PD 9216          // P*D
#define NT 160           // NCAPS*T
#define KCH1 36          // split-K chunks gemm1 (36*256 = 9216)
#define KCH2 2           // split-K chunks gemm2 (2*256 = 512)

// SMEM stage: K=64 halves (128B) + 16B pad -> 144B row stride.
// A: 64 rows, B: 160 rows.
#define SROW2 144
#define B_OFF2  9216             // 64*144
#define STAGE2  32256            // + 160*144
#define NSTAGE 3
#define SMEM_BYTES (NSTAGE*STAGE2)   // 96768 -> 2 CTAs/SM

// ---------------- scratch ----------------------------------------------------
__device__ __half g_Wt2h[PD*NT];      // fl16(W) [pd][nt] (gemm2 epilogue)
__device__ __half g_Xq[BATCH*PD];     // fl16(X) [b][pd]
__device__ __half g_Xtq[PD*BATCH];    // fl16(X)^T [pd][b]
__device__ __half g_Bq[NT*PD];        // fl16(c.W) [nt][pd]
__device__ __half g_vq[NT*BATCH];     // fl16(v) [nt][b]
__device__ float  g_s[BATCH*NT];      // atomically-accumulated s [b][nt]
__device__ float  g_bbar[P*NCAPS];
__device__ float  g_b[P*NCAPS];

// ---------------- PTX helpers ------------------------------------------------
__device__ __forceinline__ void mma16816(float* c,
    uint32_t a0, uint32_t a1, uint32_t a2, uint32_t a3,
    uint32_t b0, uint32_t b1) {
    asm volatile(
        "mma.sync.aligned.m16n8k16.row.col.f32.f16.f16.f32 "
        "{%0,%1,%2,%3}, {%4,%5,%6,%7}, {%8,%9}, {%0,%1,%2,%3};"
        : "+f"(c[0]), "+f"(c[1]), "+f"(c[2]), "+f"(c[3])
        : "r"(a0), "r"(a1), "r"(a2), "r"(a3), "r"(b0), "r"(b1));
}
__device__ __forceinline__ void ldmx4(uint32_t* r, uint32_t addr) {
    asm volatile("ldmatrix.sync.aligned.m8n8.x4.shared.b16 {%0,%1,%2,%3}, [%4];"
        : "=r"(r[0]), "=r"(r[1]), "=r"(r[2]), "=r"(r[3]) : "r"(addr));
}
__device__ __forceinline__ void ldmx2(uint32_t* r, uint32_t addr) {
    asm volatile("ldmatrix.sync.aligned.m8n8.x2.shared.b16 {%0,%1}, [%2];"
        : "=r"(r[0]), "=r"(r[1]) : "r"(addr));
}
__device__ __forceinline__ uint32_t s2u(const void* p) {
    uint32_t a;
    asm("{ .reg .u64 t; cvta.to.shared.u64 t, %1; cvt.u32.u64 %0, t; }"
        : "=r"(a) : "l"(p));
    return a;
}
__device__ __forceinline__ void cpasync16(uint32_t dst, const void* src) {
    asm volatile("cp.async.cg.shared.global [%0], [%1], 16;"
        :: "r"(dst), "l"(__cvta_generic_to_global(src)));
}
#define CP_COMMIT() asm volatile("cp.async.commit_group;" ::: "memory")
#define CP_WAIT(n)  asm volatile("cp.async.wait_group %0;" :: "n"(n) : "memory")

__device__ __forceinline__ void redg2(float* p, float a, float b) {
    asm volatile("red.global.add.v2.f32 [%0], {%1, %2};"
        :: "l"(__cvta_generic_to_global(p)), "f"(a), "f"(b) : "memory");
}
__device__ __forceinline__ float red32(float v) {
    #pragma unroll
    for (int o = 16; o > 0; o >>= 1)
        v += __shfl_xor_sync(0xffffffffu, v, o);
    return v;
}

// ---------------- fused prep -------------------------------------------------
#define PREP_WBLOCKS 360
#define PREP_XBLOCKS 4608
__global__ void __launch_bounds__(256) k_prepall(
    const float* __restrict__ W, const float* __restrict__ X) {
    int tid = threadIdx.x;
    if (blockIdx.x < PREP_WBLOCKS) {
        __shared__ float ts[256][20];      // [pd_local][t]
        int tb = blockIdx.x;
        int n  = tb / 36;
        int pd0 = (tb % 36) * 256;
        int p0 = pd0 >> 3;

        int z = tb*256 + tid;
        if (z < P*NCAPS) g_b[z] = 0.0f;
        if (z < BATCH*NT/4)
            ((float4*)g_s)[z] = make_float4(0.0f, 0.0f, 0.0f, 0.0f);

        {   // read W: 32 p-chunks x 128 contiguous floats, float4
            int chunk = tid >> 3, inner = tid & 7;
            const float* src = W + (size_t)(p0 + chunk)*(NCAPS*T*D) + n*(T*D)
                               + inner*16;
            #pragma unroll
            for (int j4 = 0; j4 < 4; ++j4) {
                float4 v = *(const float4*)(src + j4*4);
                int l0 = inner*16 + j4*4;
                int t = l0 >> 3, d = l0 & 7;
                ts[chunk*8 + d    ][t] = v.x;
                ts[chunk*8 + d + 1][t] = v.y;
                ts[chunk*8 + d + 2][t] = v.z;
                ts[chunk*8 + d + 3][t] = v.w;
            }
        }
        __syncthreads();
        {   // Wt2h [pd][nt]: 8B stores
            int lane4 = tid & 3, rbase = tid >> 2;
            #pragma unroll
            for (int rr = 0; rr < 4; ++rr) {
                int row = rbase + rr*64;
                float4 v = *(const float4*)&ts[row][lane4*4];
                __half2 ha = __floats2half2_rn(v.x, v.y);
                __half2 hb = __floats2half2_rn(v.z, v.w);
                uint2 u2;
                u2.x = *(uint32_t*)&ha; u2.y = *(uint32_t*)&hb;
                *(uint2*)&g_Wt2h[(size_t)(pd0 + row)*NT + n*16 + lane4*4] = u2;
            }
        }
        {   // Bq [nt][pd]: 32B (sector-exact) per thread
            int ntl = tid & 15, pdl = (tid >> 4) * 16;
            __half hbuf[16];
            #pragma unroll
            for (int j = 0; j < 16; ++j)
                hbuf[j] = __float2half_rn(0.1f * ts[pdl + j][ntl]);
            uint4* dst = (uint4*)&g_Bq[(size_t)(n*16 + ntl)*PD + pd0 + pdl];
            dst[0] = *(uint4*)&hbuf[0];
            dst[1] = *(uint4*)&hbuf[8];
        }
    } else {
        __shared__ __half tb2[32][33];
        int bid = blockIdx.x - PREP_WBLOCKS;
        int pd0 = (bid % (PD/32)) * 32, b0 = (bid / (PD/32)) * 32;
        int tx = tid & 31, ty = tid >> 5;
        #pragma unroll
        for (int j = 0; j < 32; j += 8) {
            float v = X[(size_t)(b0 + ty + j)*PD + pd0 + tx];
            __half h = __float2half_rn(v);
            g_Xq[(size_t)(b0 + ty + j)*PD + pd0 + tx] = h;
            tb2[ty + j][tx] = h;
        }
        __syncthreads();
        #pragma unroll
        for (int j = 0; j < 32; j += 8)
            g_Xtq[(size_t)(pd0 + ty + j)*BATCH + b0 + tx] = tb2[tx][ty + j];
    }
}

// ---------------- compute one K=64 stage -------------------------------------
// 8 warps as 2(M) x 4(N); warp tile 32(M) x 40(N); fp16 operands
__device__ __forceinline__ void compute_stage64(
    uint32_t base, int wm32, int wn40, int lane, float acc[2][5][4]) {
    int grp = lane >> 3, lr = lane & 7;
    #pragma unroll
    for (int ko = 0; ko < 64; ko += 16) {
        uint32_t bh[5][2];
        #pragma unroll
        for (int bp = 0; bp < 2; ++bp) {
            uint32_t ba = (uint32_t)((wn40 + bp*16 + ((grp & 2) << 2) + lr)*SROW2
                                     + (ko + (grp & 1)*8)*2);
            uint32_t r4[4];
            ldmx4(r4, base + B_OFF2 + ba);
            bh[bp*2][0]   = r4[0]; bh[bp*2][1]   = r4[1];
            bh[bp*2+1][0] = r4[2]; bh[bp*2+1][1] = r4[3];
        }
        {
            uint32_t ba = (uint32_t)((wn40 + 32 + lr)*SROW2 + (ko + (grp & 1)*8)*2);
            ldmx2(bh[4], base + B_OFF2 + ba);
        }
        #pragma unroll
        for (int mt = 0; mt < 2; ++mt) {
            uint32_t aa = (uint32_t)((wm32 + mt*16 + (grp & 1)*8 + lr)*SROW2
                                     + (ko + (grp >> 1)*8)*2);
            uint32_t ah[4];
            ldmx4(ah, base + aa);
            #pragma unroll
            for (int bt = 0; bt < 5; ++bt)
                mma16816(acc[mt][bt], ah[0], ah[1], ah[2], ah[3], bh[bt][0], bh[bt][1]);
        }
    }
}

// ---------------- GEMM1: g_s[b][nt] += X[64b x 256k] * Bq[256k x 160] --------
__global__ void __launch_bounds__(256, 2) k_gemm1() {
    extern __shared__ char smem[];
    uint32_t sb = s2u(smem);
    int tid = threadIdx.x;
    int wid = tid >> 5, lane = tid & 31;
    int wm32 = (wid >> 2) * 32;
    int wn40 = (wid & 3) * 40;
    int b0 = blockIdx.x * 64;
    int kc = blockIdx.y * 256;

    float acc[2][5][4];
    #pragma unroll
    for (int i = 0; i < 2; ++i)
        #pragma unroll
        for (int j = 0; j < 5; ++j)
            #pragma unroll
            for (int r = 0; r < 4; ++r) acc[i][j][r] = 0.0f;

    auto issue = [&](int s, int buf) {
        int kb = kc + s*64;
        uint32_t base = sb + buf*STAGE2;
        #pragma unroll
        for (int u = 0; u < 2; ++u) {    // A: 64 rows x 8 chunks = 512
            int ch = tid*2 + u, row = ch >> 3, q = ch & 7;
            cpasync16(base + row*SROW2 + q*16,
                      g_Xq + (size_t)(b0 + row)*PD + kb + q*8);
        }
        #pragma unroll
        for (int u = 0; u < 5; ++u) {    // B: 160 rows x 8 = 1280
            int ch = tid + 256*u, row = ch >> 3, q = ch & 7;
            cpasync16(base + B_OFF2 + row*SROW2 + q*16,
                      g_Bq + (size_t)row*PD + kb + q*8);
        }
    };

    issue(0, 0); CP_COMMIT();
    issue(1, 1); CP_COMMIT();
    #pragma unroll 1
    for (int s = 0; s < 4; ++s) {
        if (s < 3) CP_WAIT(1); else CP_WAIT(0);
        __syncthreads();
        if (s + 2 < 4) { issue(s + 2, (s + 2) % NSTAGE); CP_COMMIT(); }
        compute_stage64(sb + (s % NSTAGE)*STAGE2, wm32, wn40, lane, acc);
    }

    int g = lane >> 2, qq = (lane & 3)*2;
    #pragma unroll
    for (int mt = 0; mt < 2; ++mt) {
        int row = b0 + wm32 + mt*16 + g;
        #pragma unroll
        for (int bt = 0; bt < 5; ++bt) {
            int col = wn40 + bt*8 + qq;
            redg2(&g_s[(size_t)row*NT + col],     acc[mt][bt][0], acc[mt][bt][1]);
            redg2(&g_s[(size_t)(row+8)*NT + col], acc[mt][bt][2], acc[mt][bt][3]);
        }
    }
}

// ---------------- GEMM2 + fused agreement epilogue ---------------------------
// Wt2h tile (64 x 160 fp16 = 20480B) prefetched at s==2 into retired buf1.
__global__ void __launch_bounds__(256, 2) k_gemm2() {
    extern __shared__ char smem[];
    uint32_t sb = s2u(smem);
    int tid = threadIdx.x;
    int wid = tid >> 5, lane = tid & 31;
    int wm32 = (wid >> 2) * 32;
    int wn40 = (wid & 3) * 40;
    int pd0 = blockIdx.x * 64;
    int kc = blockIdx.y * 256;

    float acc[2][5][4];
    #pragma unroll
    for (int i = 0; i < 2; ++i)
        #pragma unroll
        for (int j = 0; j < 5; ++j)
            #pragma unroll
            for (int r = 0; r < 4; ++r) acc[i][j][r] = 0.0f;

    auto issue = [&](int s, int buf) {
        int kb = kc + s*64;
        uint32_t base = sb + buf*STAGE2;
        #pragma unroll
        for (int u = 0; u < 2; ++u) {
            int ch = tid*2 + u, row = ch >> 3, q = ch & 7;
            cpasync16(base + row*SROW2 + q*16,
                      g_Xtq + (size_t)(pd0 + row)*BATCH + kb + q*8);
        }
        #pragma unroll
        for (int u = 0; u < 5; ++u) {
            int ch = tid + 256*u, row = ch >> 3, q = ch & 7;
            cpasync16(base + B_OFF2 + row*SROW2 + q*16,
                      g_vq + (size_t)row*BATCH + kb + q*8);
        }
    };
    // Wt2h tile -> buf1 (retired after s==1): 1280 x 16B chunks, 20/row
    auto issue_wt2 = [&]() {
        #pragma unroll
        for (int u = 0; u < 5; ++u) {
            int ch = tid + 256*u;
            int row = ch / 20, c = ch % 20;
            cpasync16(sb + STAGE2 + ch*16,
                      g_Wt2h + (size_t)(pd0 + row)*NT + c*8);
        }
    };

    issue(0, 0); CP_COMMIT();
    issue(1, 1); CP_COMMIT();
    #pragma unroll 1
    for (int s = 0; s < 4; ++s) {
        if (s < 3) CP_WAIT(1); else CP_WAIT(0);
        __syncthreads();
        if (s + 2 < 4)      { issue(s + 2, (s + 2) % NSTAGE); CP_COMMIT(); }
        else if (s == 2)    { issue_wt2(); CP_COMMIT(); }
        compute_stage64(sb + (s % NSTAGE)*STAGE2, wm32, wn40, lane, acc);
    }
    CP_WAIT(0);
    __syncthreads();

    const __half* wth = (const __half*)(smem + STAGE2);   // Wt2h tile [64][160]
    int g = lane >> 2, qq = (lane & 3)*2;
    #pragma unroll
    for (int mt = 0; mt < 2; ++mt) {
        int r0 = wm32 + mt*16 + g;
        int pg = (pd0 + wm32 + mt*16) >> 3;
        float v0 = 0.0f, v1 = 0.0f;
        int curn = wn40 >> 4;
        #pragma unroll
        for (int bt = 0; bt < 5; ++bt) {
            int colb = wn40 + bt*8;
            int n = colb >> 4;
            if (n != curn) {                     // warp-uniform branch
                float s0 = red32(v0), s1 = red32(v1);
                if (lane == 0) {
                    atomicAdd(&g_bbar[pg*NCAPS + curn], s0);
                    atomicAdd(&g_bbar[(pg + 1)*NCAPS + curn], s1);
                }
                v0 = v1 = 0.0f;
                curn = n;
            }
            int col = colb + qq;
            float2 w0 = __half22float2(*(const __half2*)&wth[r0*NT + col]);
            float2 w1 = __half22float2(*(const __half2*)&wth[(r0 + 8)*NT + col]);
            v0 += acc[mt][bt][0]*w0.x + acc[mt][bt][1]*w0.y;
            v1 += acc[mt][bt][2]*w1.x + acc[mt][bt][3]*w1.y;
        }
        {
            float s0 = red32(v0), s1 = red32(v1);
            if (lane == 0) {
                atomicAdd(&g_bbar[pg*NCAPS + curn], s0);
                atomicAdd(&g_bbar[(pg + 1)*NCAPS + curn], s1);
            }
        }
    }
}

// ---------------- squash (reads g_s, zeroes it for next iter) ----------------
__global__ void k_redsquash(float* __restrict__ out, int final_it) {
    int i4 = blockIdx.x * blockDim.x + threadIdx.x;   // [0, BATCH*NT/4)
    float4 s = ((const float4*)g_s)[i4];
    float ss = s.x*s.x + s.y*s.y + s.z*s.z + s.w*s.w;
    #pragma unroll
    for (int o = 1; o < 4; o <<= 1)
        ss += __shfl_xor_sync(0xffffffffu, ss, o);    // 4 lanes x 4 = 16 t's
    float nrm = sqrtf(ss);
    float f = ss / (1.0f + ss*(nrm + 1e-9f));
    float4 v = make_float4(f*s.x, f*s.y, f*s.z, f*s.w);
    if (final_it) {
        ((float4*)out)[i4] = v;
    } else {
        ((float4*)g_s)[i4] = make_float4(0.0f, 0.0f, 0.0f, 0.0f);
        int idx = 4*i4;
        int b = idx / NT, nt = idx - b*NT;
        g_vq[(size_t)nt*BATCH + b]     = __float2half_rn(v.x);
        g_vq[(size_t)(nt+1)*BATCH + b] = __float2half_rn(v.y);
        g_vq[(size_t)(nt+2)*BATCH + b] = __float2half_rn(v.z);
        g_vq[(size_t)(nt+3)*BATCH + b] = __float2half_rn(v.w);
        if (i4 < P*NCAPS/4)
            ((float4*)g_bbar)[i4] = make_float4(0.0f, 0.0f, 0.0f, 0.0f);
    }
}

// ---------------- fused route (softmax) + B quantize -------------------------
__global__ void __launch_bounds__(256) k_routesplitB(const float* __restrict__ W) {
    __shared__ float sbn[8][10];
    __shared__ float sc[8][10];
    int tid = threadIdx.x;
    int p0 = blockIdx.x * 8;
    int pd0 = blockIdx.x * 64;

    if (tid < 80) {
        int lp = tid / 10, n = tid - lp*10;
        int p = p0 + lp;
        float bn = g_b[p*NCAPS + n] + g_bbar[p*NCAPS + n] * (1.0f / (float)BATCH);
        g_b[p*NCAPS + n] = bn;
        sbn[lp][n] = bn;
    }
    __syncthreads();
    if (tid < 8) {
        float mx = -1e30f;
        #pragma unroll
        for (int n = 0; n < NCAPS; ++n) mx = fmaxf(mx, sbn[tid][n]);
        float sum = 0.0f;
        float e[NCAPS];
        #pragma unroll
        for (int n = 0; n < NCAPS; ++n) { e[n] = expf(sbn[tid][n] - mx); sum += e[n]; }
        float rs = 1.0f / sum;
        #pragma unroll
        for (int n = 0; n < NCAPS; ++n) sc[tid][n] = e[n]*rs;
    }
    __syncthreads();

    #pragma unroll
    for (int u = 0; u < 10; ++u) {
        int fl = tid + 256*u;          // 0..2559: 160 nt x 16 pd-quads
        int nt = fl >> 4, pdq = fl & 15;
        int n = nt >> 4, t = nt & 15;
        int p = p0 + (pdq >> 1), d0 = (pdq & 1)*4;
        float c = sc[pdq >> 1][n];
        float4 w = *(const float4*)&W[((p*NCAPS + n)*T + t)*D + d0];
        size_t base = (size_t)nt*PD + pd0 + pdq*4;
        *(__half2*)&g_Bq[base]     = __floats2half2_rn(w.x*c, w.y*c);
        *(__half2*)&g_Bq[base + 2] = __floats2half2_rn(w.z*c, w.w*c);
    }
}

// ---------------- launch -----------------------------------------------------
extern "C" void kernel_launch(void* const* d_in, const int* in_sizes, int n_in,
                              void* d_out, int out_size) {
    (void)in_sizes; (void)n_in; (void)out_size;
    const float* x = (const float*)d_in[0];   // [512, 1152, 8]
    const float* W = (const float*)d_in[1];   // [1152, 10, 16, 8]
    float* out = (float*)d_out;               // [512, 10, 16, 1]

    cudaFuncSetAttribute((const void*)k_gemm1,
                         cudaFuncAttributeMaxDynamicSharedMemorySize, SMEM_BYTES);
    cudaFuncSetAttribute((const void*)k_gemm2,
                         cudaFuncAttributeMaxDynamicSharedMemorySize, SMEM_BYTES);

    k_prepall<<<PREP_WBLOCKS + PREP_XBLOCKS, 256>>>(W, x);

    for (int it = 0; it < 3; ++it) {
        k_gemm1<<<dim3(BATCH/64, KCH1), 256, SMEM_BYTES>>>();
        k_redsquash<<<(BATCH*NT/4)/128, 128>>>(out, it == 2 ? 1 : 0);
        if (it < 2) {
            k_gemm2<<<dim3(PD/64, KCH2), 256, SMEM_BYTES>>>();
            k_routesplitB<<<P/8, 256>>>(W);
        }
    }
}